// round 1
// baseline (speedup 1.0000x reference)
#include <cuda_runtime.h>

#define N_RES 2048
#define BATCH 16
#define LMAXP 13
#define NTYPES 20

__constant__ int c_reslen[NTYPES] = {3, 4, 5, 5, 6, 6, 6, 7, 7, 7, 7, 7, 8, 8, 8, 9, 10, 10, 11, 13};

__device__ int g_starts[N_RES];

// ---------------------------------------------------------------------------
// Kernel 1: exclusive prefix-sum of residue lengths -> g_starts
// 1 block, 1024 threads, each handles 2 residues. shfl warp scan + warp-sum scan.
// ---------------------------------------------------------------------------
__global__ void scan_kernel(const int* __restrict__ seq) {
    int t = threadIdx.x;  // 0..1023
    int l0 = c_reslen[seq[2 * t]];
    int l1 = c_reslen[seq[2 * t + 1]];
    int a = l0 + l1;

    // warp-inclusive scan of a
    int v = a;
#pragma unroll
    for (int off = 1; off < 32; off <<= 1) {
        int n = __shfl_up_sync(0xFFFFFFFFu, v, off);
        if ((t & 31) >= off) v += n;
    }

    __shared__ int wsum[32];
    if ((t & 31) == 31) wsum[t >> 5] = v;
    __syncthreads();
    if (t < 32) {
        int s = wsum[t];
        int x = s;
#pragma unroll
        for (int off = 1; off < 32; off <<= 1) {
            int n = __shfl_up_sync(0xFFFFFFFFu, x, off);
            if (t >= off) x += n;
        }
        wsum[t] = x - s;  // exclusive warp offset
    }
    __syncthreads();

    int excl = wsum[t >> 5] + (v - a);  // exclusive prefix over pairs
    g_starts[2 * t] = excl;
    g_starts[2 * t + 1] = excl + l0;
}

// ---------------------------------------------------------------------------
// Kernel 2: one block per residue.
//   diff[b][l][.] staged in smem (float4-padded), weight rows kept in regs,
//   batch loop outer with diffs in regs -> pure FFMA inner loops.
// ---------------------------------------------------------------------------
template <int L>
__device__ __forceinline__ void do_residue(
    int i, int t, int start, int atoms,
    const float4* __restrict__ sdiff,   // [BATCH][LMAXP]
    const float* __restrict__ W_amn,
    const float* __restrict__ W_atm,
    float* __restrict__ out_atm,
    float* __restrict__ out_amn)
{
    constexpr int NPAIRS = 64 + L * 64;                 // amn 'o' pairs + atm (m,v) pairs
    constexpr int NP = (NPAIRS + 255) / 256;            // pairs per thread (ceil)
    const int tid = threadIdx.x;

    float  w[NP][L];
    float* base[NP];
    size_t bstr[NP];
    bool   valid[NP];

#pragma unroll
    for (int j = 0; j < NP; j++) {
        int p0 = tid + j * 256;
        valid[j] = (p0 < NPAIRS);
        if (valid[j]) {
            if (p0 < 64) {
                const float* Wa = W_amn + ((size_t)t * 64 + p0) * LMAXP;
#pragma unroll
                for (int l = 0; l < L; l++) w[j][l] = Wa[l];
                base[j] = out_amn + (size_t)i * 192 + p0 * 3;
                bstr[j] = (size_t)N_RES * 192;
            } else {
                int p = p0 - 64;
                int m = p >> 6;
                int vv = p & 63;
                const float* Wt = W_atm + (((size_t)t * LMAXP + m) * 64 + vv) * LMAXP;
#pragma unroll
                for (int l = 0; l < L; l++) w[j][l] = Wt[l];
                base[j] = out_atm + (size_t)(start + m) * 192 + vv * 3;
                bstr[j] = (size_t)atoms * 192;
            }
        }
    }

#pragma unroll 1
    for (int b = 0; b < BATCH; b++) {
        float dx[L], dy[L], dz[L];
#pragma unroll
        for (int l = 0; l < L; l++) {
            float4 v4 = sdiff[b * LMAXP + l];
            dx[l] = v4.x; dy[l] = v4.y; dz[l] = v4.z;
        }
#pragma unroll
        for (int j = 0; j < NP; j++) {
            if (!valid[j]) continue;
            float a0 = 0.f, a1 = 0.f, a2 = 0.f;
#pragma unroll
            for (int l = 0; l < L; l++) {
                a0 = fmaf(w[j][l], dx[l], a0);
                a1 = fmaf(w[j][l], dy[l], a1);
                a2 = fmaf(w[j][l], dz[l], a2);
            }
            float* o = base[j] + (size_t)b * bstr[j];
            o[0] = a0; o[1] = a1; o[2] = a2;
        }
    }
}

__global__ void __launch_bounds__(256, 2) posmix_kernel(
    const float* __restrict__ pos_atm,
    const float* __restrict__ pos_amn,
    const float* __restrict__ W_amn,
    const float* __restrict__ W_atm,
    const int* __restrict__ seq,
    float* __restrict__ out_atm,
    float* __restrict__ out_amn,
    int atoms)
{
    __shared__ float4 sdiff[BATCH * LMAXP];

    const int i = blockIdx.x;
    const int t = seq[i];
    const int L = c_reslen[t];
    const int start = g_starts[i];
    const int tid = threadIdx.x;

    // stage diffs: (b, l) pairs
    const int tot = BATCH * L;
    for (int idx = tid; idx < tot; idx += 256) {
        int b = idx / L, l = idx - b * L;
        const float* pa = pos_atm + ((size_t)b * atoms + start + l) * 3;
        const float* pm = pos_amn + ((size_t)b * N_RES + i) * 3;
        sdiff[b * LMAXP + l] = make_float4(pa[0] - pm[0], pa[1] - pm[1], pa[2] - pm[2], 0.f);
    }
    __syncthreads();

    switch (L) {
        case 3:  do_residue<3>(i, t, start, atoms, sdiff, W_amn, W_atm, out_atm, out_amn); break;
        case 4:  do_residue<4 >(i, t, start, atoms, sdiff, W_amn, W_atm, out_atm, out_amn); break;
        case 5:  do_residue<5 >(i, t, start, atoms, sdiff, W_amn, W_atm, out_atm, out_amn); break;
        case 6:  do_residue<6 >(i, t, start, atoms, sdiff, W_amn, W_atm, out_atm, out_amn); break;
        case 7:  do_residue<7 >(i, t, start, atoms, sdiff, W_amn, W_atm, out_atm, out_amn); break;
        case 8:  do_residue<8 >(i, t, start, atoms, sdiff, W_amn, W_atm, out_atm, out_amn); break;
        case 9:  do_residue<9 >(i, t, start, atoms, sdiff, W_amn, W_atm, out_atm, out_amn); break;
        case 10: do_residue<10>(i, t, start, atoms, sdiff, W_amn, W_atm, out_atm, out_amn); break;
        case 11: do_residue<11>(i, t, start, atoms, sdiff, W_amn, W_atm, out_atm, out_amn); break;
        case 13: do_residue<13>(i, t, start, atoms, sdiff, W_amn, W_atm, out_atm, out_amn); break;
        default: break;
    }
}

// ---------------------------------------------------------------------------
// Launch
// in: 0 pos_atm (B, atoms, 3) f32
//     1 pos_amn (B, 2048, 3) f32
//     2 W_amn   (20, 64, 13) f32
//     3 W_atm   (20, 13, 64, 13) f32
//     4 seq_types (2048,) i32
// out: [x_v_atm (B, atoms, 64, 3) | x_v_amn (B, 2048, 64, 3)] f32
// ---------------------------------------------------------------------------
extern "C" void kernel_launch(void* const* d_in, const int* in_sizes, int n_in,
                              void* d_out, int out_size)
{
    const float* pos_atm = (const float*)d_in[0];
    const float* pos_amn = (const float*)d_in[1];
    const float* W_amn   = (const float*)d_in[2];
    const float* W_atm   = (const float*)d_in[3];
    const int*   seq     = (const int*)d_in[4];

    const int atoms = in_sizes[0] / (BATCH * 3);

    float* out_atm = (float*)d_out;
    float* out_amn = out_atm + (size_t)BATCH * atoms * 64 * 3;

    scan_kernel<<<1, 1024>>>(seq);
    posmix_kernel<<<N_RES, 256>>>(pos_atm, pos_amn, W_amn, W_atm, seq,
                                  out_atm, out_amn, atoms);
}